// round 1
// baseline (speedup 1.0000x reference)
#include <cuda_runtime.h>
#include <cstdint>

#define T_TREES 100
#define NN      31
#define D       256
#define BATCH   8192
#define NU      16                 // nodes actually used per tree (0..15)
#define ROWS    (T_TREES * NU)     // 1600 virtual GEMM rows
#define NLEAF   32
#define NC      64

// ---------------- scratch (static __device__, no allocation) ----------------
__device__ float   g_xT[D * BATCH];            // 8 MB transposed x: [k][b]
__device__ uint8_t g_leaf[T_TREES * BATCH];    // 800 KB leaf indices [t][b]

// ---------------- kernel 0: transpose x[B][D] -> xT[D][B] ----------------
__global__ void k_transpose(const float* __restrict__ x) {
    __shared__ float tile[32][33];
    int bk = blockIdx.x * 32;      // over D
    int bb = blockIdx.y * 32;      // over B
    int tx = threadIdx.x, ty = threadIdx.y;   // 32 x 8
#pragma unroll
    for (int j = 0; j < 32; j += 8)
        tile[ty + j][tx] = x[(bb + ty + j) * D + bk + tx];
    __syncthreads();
#pragma unroll
    for (int j = 0; j < 32; j += 8)
        g_xT[(size_t)(bk + ty + j) * BATCH + bb + tx] = tile[tx][ty + j];
}

// ---------------- kernel 1: node scores (GEMM) + tree traversal ----------------
#define BM 64
#define BN 256
#define BK 32
#define NCHUNK (D / BK)            // 8

#define WS_STRIDE 36               // padded row (floats), 144B: 16B-aligned
#define WS_BUF (BM * WS_STRIDE)    // 2304 floats per buffer
#define XS_BUF (BK * BN)           // 8192 floats per buffer
#define SMEM_FLOATS (2 * WS_BUF + 2 * XS_BUF + 64)
#define SMEM_BYTES  (SMEM_FLOATS * 4)   // 84224 B

__device__ __forceinline__ void cp16(uint32_t dst, const void* src) {
    asm volatile("cp.async.cg.shared.global [%0], [%1], 16;\n" :: "r"(dst), "l"(src));
}
__device__ __forceinline__ void cp_commit() {
    asm volatile("cp.async.commit_group;\n");
}
template <int N> __device__ __forceinline__ void cp_wait() {
    asm volatile("cp.async.wait_group %0;\n" :: "n"(N));
}

__global__ __launch_bounds__(256, 2)
void k_forest_nodes(const float* __restrict__ node_w,
                    const float* __restrict__ node_b) {
    extern __shared__ float sm[];
    float* ws = sm;                               // [2][BM][WS_STRIDE]
    float* xs = sm + 2 * WS_BUF;                  // [2][BK][BN]
    float* bs = sm + 2 * WS_BUF + 2 * XS_BUF;     // [64] biases (4 trees x 16)

    const int tid = threadIdx.x;
    const int m0  = blockIdx.x * BM;              // virtual row tile
    const int n0  = blockIdx.y * BN;              // sample tile
    const int T0  = m0 >> 4;                      // first tree of this tile

    if (tid < 64)
        bs[tid] = node_b[(T0 + (tid >> 4)) * NN + (tid & 15)];

    const uint32_t ws_sh = (uint32_t)__cvta_generic_to_shared(ws);
    const uint32_t xs_sh = (uint32_t)__cvta_generic_to_shared(xs);

    auto load_chunk = [&](int kb, int buf) {
        const int k0 = kb * BK;
        // W: 64 rows x 32 k = 512 x 16B copies (row-major, no transpose)
#pragma unroll
        for (int r = 0; r < 2; r++) {
            int op  = tid + 256 * r;              // 0..511
            int row = op >> 3, k4 = op & 7;
            int vr  = m0 + row;
            int g   = (vr >> 4) * NN + (vr & 15); // tree*31 + node
            cp16(ws_sh + (uint32_t)(buf * WS_BUF + row * WS_STRIDE + k4 * 4) * 4,
                 node_w + (size_t)g * D + k0 + k4 * 4);
        }
        // X: 32 k-rows x 256 samples = 2048 x 16B copies (already transposed)
#pragma unroll
        for (int r = 0; r < 8; r++) {
            int op = tid + 256 * r;
            int k  = op >> 6, sg = op & 63;
            cp16(xs_sh + (uint32_t)(buf * XS_BUF + k * BN + sg * 4) * 4,
                 g_xT + (size_t)(k0 + k) * BATCH + n0 + sg * 4);
        }
        cp_commit();
    };

    load_chunk(0, 0);
    load_chunk(1, 1);

    const int lane = tid & 31;
    const int wrow = (tid >> 5) * 8;              // this warp's 8 node-rows

    // accumulators: 8 rows x 8 samples as 4 packed f32x2 per row
    unsigned long long acc[8][4];
#pragma unroll
    for (int i = 0; i < 8; i++)
#pragma unroll
        for (int j = 0; j < 4; j++) acc[i][j] = 0ull;

    for (int kb = 0; kb < NCHUNK; kb++) {
        if (kb == NCHUNK - 1) cp_wait<0>(); else cp_wait<1>();
        __syncthreads();

        const float* wsb = ws + (kb & 1) * WS_BUF;
        const float* xsb = xs + (kb & 1) * XS_BUF;

#pragma unroll 8
        for (int k = 0; k < BK; k++) {
            // two packed sample quads: samples 4*lane.. and 128+4*lane..
            ulonglong2 xa = *(const ulonglong2*)(xsb + k * BN + 4 * lane);
            ulonglong2 xb = *(const ulonglong2*)(xsb + k * BN + 128 + 4 * lane);
#pragma unroll
            for (int i = 0; i < 8; i++) {
                uint32_t wv = *(const uint32_t*)(wsb + (wrow + i) * WS_STRIDE + k);
                unsigned long long wd;
                asm("mov.b64 %0, {%1, %1};" : "=l"(wd) : "r"(wv));
                asm("fma.rn.f32x2 %0, %1, %2, %0;" : "+l"(acc[i][0]) : "l"(wd), "l"(xa.x));
                asm("fma.rn.f32x2 %0, %1, %2, %0;" : "+l"(acc[i][1]) : "l"(wd), "l"(xa.y));
                asm("fma.rn.f32x2 %0, %1, %2, %0;" : "+l"(acc[i][2]) : "l"(wd), "l"(xb.x));
                asm("fma.rn.f32x2 %0, %1, %2, %0;" : "+l"(acc[i][3]) : "l"(wd), "l"(xb.y));
            }
        }
        __syncthreads();
        if (kb + 2 < NCHUNK) load_chunk(kb + 2, kb & 1);
    }

    // ---- epilogue: dump scores to smem (reuse xs region), then traverse ----
    float* sc = xs;                                // [64][256]
#pragma unroll
    for (int i = 0; i < 8; i++) {
        ulonglong2 v0; v0.x = acc[i][0]; v0.y = acc[i][1];
        ulonglong2 v1; v1.x = acc[i][2]; v1.y = acc[i][3];
        *(ulonglong2*)(sc + (wrow + i) * BN + 4 * lane) = v0;
        *(ulonglong2*)(sc + (wrow + i) * BN + 128 + 4 * lane) = v1;
    }
    __syncthreads();

    const int s = tid;                             // one sample per thread
#pragma unroll
    for (int tt = 0; tt < 4; tt++) {
        int idx = 0;
#pragma unroll
        for (int l = 0; l < 5; l++) {
            float z = sc[((tt << 4) + idx) * BN + s] + bs[(tt << 4) + idx];
            idx = 2 * idx + (z <= 0.0f ? 1 : 0);   // sigmoid(z)<=0.5 <=> z<=0
        }
        g_leaf[(size_t)(T0 + tt) * BATCH + n0 + s] = (uint8_t)idx;
    }
}

// ---------------- kernel 2: leaf gather + forest mean ----------------
__global__ void k_gather(const float* __restrict__ leaves, float* __restrict__ out) {
    __shared__ uint8_t sidx[T_TREES * 32];        // 3200 B
    const int s0  = blockIdx.x * 32;
    const int tid = threadIdx.x;

    // stage leaf indices for this sample tile: [t][s_local]
    for (int i = tid; i < T_TREES * 32 / 4; i += 256) {
        int t = i >> 3, w = i & 7;
        ((uint32_t*)sidx)[i] =
            *(const uint32_t*)(g_leaf + (size_t)t * BATCH + s0 + w * 4);
    }
    __syncthreads();

    const int s  = tid >> 3;     // 32 samples
    const int c8 = tid & 7;      // 8 class-groups of 8 classes
    float4 a0 = make_float4(0.f, 0.f, 0.f, 0.f);
    float4 a1 = make_float4(0.f, 0.f, 0.f, 0.f);

#pragma unroll 4
    for (int t = 0; t < T_TREES; t++) {
        int idx = sidx[t * 32 + s];
        const float4* lp =
            (const float4*)(leaves + ((size_t)(t * NLEAF + idx)) * NC + c8 * 8);
        float4 v0 = lp[0], v1 = lp[1];
        a0.x += v0.x; a0.y += v0.y; a0.z += v0.z; a0.w += v0.w;
        a1.x += v1.x; a1.y += v1.y; a1.z += v1.z; a1.w += v1.w;
    }

    const float scl = 1.0f / (float)T_TREES;
    float4* op = (float4*)(out + (size_t)(s0 + s) * NC + c8 * 8);
    float4 r0 = make_float4(a0.x * scl, a0.y * scl, a0.z * scl, a0.w * scl);
    float4 r1 = make_float4(a1.x * scl, a1.y * scl, a1.z * scl, a1.w * scl);
    op[0] = r0;
    op[1] = r1;
}

// ---------------- launch ----------------
extern "C" void kernel_launch(void* const* d_in, const int* in_sizes, int n_in,
                              void* d_out, int out_size) {
    const float* x      = (const float*)d_in[0];   // [8192,256]
    const float* node_w = (const float*)d_in[1];   // [100,31,256]
    const float* node_b = (const float*)d_in[2];   // [100,31]
    const float* leaves = (const float*)d_in[3];   // [100,32,64]
    float* out = (float*)d_out;                    // [8192,64]

    k_transpose<<<dim3(D / 32, BATCH / 32), dim3(32, 8)>>>(x);

    cudaFuncSetAttribute(k_forest_nodes,
                         cudaFuncAttributeMaxDynamicSharedMemorySize, SMEM_BYTES);
    k_forest_nodes<<<dim3(ROWS / BM, BATCH / BN), 256, SMEM_BYTES>>>(node_w, node_b);

    k_gather<<<BATCH / 32, 256>>>(leaves, out);
}